// round 14
// baseline (speedup 1.0000x reference)
#include <cuda_runtime.h>

#define BB 512
#define TT 256

typedef unsigned long long u64;

// Inter-layer hidden sequences, batch-major [B, T, H]. Max H=256 -> 128 MB each.
__device__ float g_bufA[BB * TT * 256];
__device__ float g_bufB[BB * TT * 256];

__device__ __forceinline__ void ffma2(u64& d, u64 a, u64 b) {
    asm("fma.rn.f32x2 %0, %1, %2, %0;" : "+l"(d) : "l"(a), "l"(b));
}
__device__ __forceinline__ u64 dup2(float w) {
    u64 r;
    unsigned int wu = __float_as_uint(w);
    asm("mov.b64 %0, {%1, %1};" : "=l"(r) : "r"(wu));
    return r;
}

// ============================================================================
// SCALAR kernel (layer 1: measured best at 512 thr / P=4, all weights in regs).
// ============================================================================
template<int FIN, int H, int P, int KREG, int THREADS>
__global__ void __launch_bounds__(THREADS, 1)
rnn_layer(const float* __restrict__ x, const float* __restrict__ Wx,
          const float* __restrict__ Wh, const float* __restrict__ bias,
          float* __restrict__ hout)
{
    constexpr int BT  = 4;
    constexpr int KV  = FIN + H;
    constexpr int KS  = KV / P;
    constexpr int KSM = KS - KREG;
    constexpr int CNT  = (BT * H + THREADS - 1) / THREADS;
    constexpr int CNTX = (BT * FIN + THREADS - 1) / THREADS;
    static_assert(H * P == THREADS, "thread count");
    static_assert(KV % P == 0 && KSM >= 0, "k partition");

    extern __shared__ float ws[];                       // [P][KSM][H]
    __shared__ __align__(16) float4 buf[2][KV];
    __shared__ float part[P][BT][H];

    const int tid = threadIdx.x;
    const int j   = tid % H;
    const int p   = tid / H;
    const int b0  = blockIdx.x * BT;
    const int k0  = p * KS;

    float w[KREG > 0 ? KREG : 1];
    #pragma unroll
    for (int q = 0; q < KREG; ++q) {
        int v = k0 + q;
        w[q] = (v < FIN) ? __ldg(&Wx[v * H + j]) : __ldg(&Wh[(v - FIN) * H + j]);
    }
    if (KSM > 0) {
        for (int idx = tid; idx < P * KSM * H; idx += THREADS) {
            int pp = idx / (KSM * H);
            int rem = idx % (KSM * H);
            int s = rem / H, jj = rem % H;
            int v = pp * KS + KREG + s;
            ws[idx] = (v < FIN) ? Wx[v * H + jj] : Wh[(v - FIN) * H + jj];
        }
    }
    for (int i = tid; i < H; i += THREADS) buf[0][FIN + i] = make_float4(0.f, 0.f, 0.f, 0.f);
    #pragma unroll
    for (int q = 0; q < CNTX; ++q) {
        int i = tid + q * THREADS;
        if (i < BT * FIN) {
            int r = i / FIN, k = i % FIN;
            ((float*)buf[0])[k * 4 + r] = __ldcg(&x[((b0 + r) * TT + 0) * FIN + k]);
        }
    }
    float bj[CNT];
    #pragma unroll
    for (int q = 0; q < CNT; ++q) {
        int e = tid + q * THREADS;
        bj[q] = (e < BT * H) ? bias[e % H] : 0.f;
    }

    __syncthreads();

    int cb = 0;

    for (int t = 0; t < TT; ++t) {
        const int nb = cb ^ 1;

        float xst[CNTX];
        if (t + 1 < TT) {
            #pragma unroll
            for (int q = 0; q < CNTX; ++q) {
                int i = tid + q * THREADS;
                if (i < BT * FIN)
                    xst[q] = __ldcg(&x[((b0 + i / FIN) * TT + (t + 1)) * FIN + (i % FIN)]);
            }
        }

        float a0 = 0.f, a1 = 0.f, a2 = 0.f, a3 = 0.f;
        const float4* ub = buf[cb] + k0;

        #pragma unroll
        for (int q = 0; q < KREG; ++q) {
            float4 v = ub[q];
            a0 = fmaf(v.x, w[q], a0);
            a1 = fmaf(v.y, w[q], a1);
            a2 = fmaf(v.z, w[q], a2);
            a3 = fmaf(v.w, w[q], a3);
        }
        if (KSM > 0) {
            const float* wsp = ws + (p * KSM) * H + j;
            #pragma unroll 8
            for (int s = 0; s < KSM; ++s) {
                float4 v = ub[KREG + s];
                float wv = wsp[s * H];
                a0 = fmaf(v.x, wv, a0);
                a1 = fmaf(v.y, wv, a1);
                a2 = fmaf(v.z, wv, a2);
                a3 = fmaf(v.w, wv, a3);
            }
        }

        part[p][0][j] = a0;
        part[p][1][j] = a1;
        part[p][2][j] = a2;
        part[p][3][j] = a3;
        if (t + 1 < TT) {
            #pragma unroll
            for (int q = 0; q < CNTX; ++q) {
                int i = tid + q * THREADS;
                if (i < BT * FIN)
                    ((float*)buf[nb])[(i % FIN) * 4 + (i / FIN)] = xst[q];
            }
        }
        __syncthreads();

        #pragma unroll
        for (int q = 0; q < CNT; ++q) {
            int e = tid + q * THREADS;
            if (e < BT * H) {
                int r = e / H, jj = e % H;
                float s = bj[q];
                #pragma unroll
                for (int pp = 0; pp < P; ++pp) s += part[pp][r][jj];
                s = fmaxf(s, 0.f);
                ((float*)buf[nb])[(FIN + jj) * 4 + r] = s;
                __stcg(&hout[((b0 + r) * TT + t) * H + jj], s);
            }
        }
        __syncthreads();
        cb = nb;
    }
}

// ============================================================================
// MOVDUP-FFMA2, P==1 (layer 2: R10 measured best, ~820us). One barrier/step.
// ============================================================================
template<int FIN, int H, int KREG, int THREADS>
__global__ void __launch_bounds__(THREADS, 1)
rnn_layer_md1(const float* __restrict__ x, const float* __restrict__ Wx,
              const float* __restrict__ Wh, const float* __restrict__ bias,
              float* __restrict__ hout)
{
    constexpr int BT  = 4;
    constexpr int KV  = FIN + H;
    constexpr int KSM = KV - KREG;
    constexpr int CNTX = (BT * FIN + THREADS - 1) / THREADS;
    static_assert(H == THREADS, "P==1: one thread per column");
    static_assert(KSM >= 0, "k partition");

    extern __shared__ float ws[];                       // [KSM][H]
    __shared__ __align__(16) float4 buf[2][KV];

    const int tid = threadIdx.x;
    const int j   = tid;
    const int b0  = blockIdx.x * BT;

    float w[KREG];
    #pragma unroll
    for (int q = 0; q < KREG; ++q) {
        int v = q;
        w[q] = (v < FIN) ? __ldg(&Wx[v * H + j]) : __ldg(&Wh[(v - FIN) * H + j]);
    }
    if (KSM > 0) {
        for (int idx = tid; idx < KSM * H; idx += THREADS) {
            int s = idx / H, jj = idx % H;
            int v = KREG + s;
            ws[idx] = (v < FIN) ? Wx[v * H + jj] : Wh[(v - FIN) * H + jj];
        }
    }
    for (int i = tid; i < H; i += THREADS) buf[0][FIN + i] = make_float4(0.f, 0.f, 0.f, 0.f);
    #pragma unroll
    for (int q = 0; q < CNTX; ++q) {
        int i = tid + q * THREADS;
        if (i < BT * FIN) {
            int r = i / FIN, k = i % FIN;
            ((float*)buf[0])[k * 4 + r] = __ldcg(&x[((b0 + r) * TT + 0) * FIN + k]);
        }
    }
    const float bjj = bias[j];

    __syncthreads();

    int cb = 0;

    for (int t = 0; t < TT; ++t) {
        const int nb = cb ^ 1;

        float xst[CNTX];
        if (t + 1 < TT) {
            #pragma unroll
            for (int q = 0; q < CNTX; ++q) {
                int i = tid + q * THREADS;
                if (i < BT * FIN)
                    xst[q] = __ldcg(&x[((b0 + i / FIN) * TT + (t + 1)) * FIN + (i % FIN)]);
            }
        }

        u64 a01 = 0, a23 = 0;
        const ulonglong2* ub = (const ulonglong2*)buf[cb];

        #pragma unroll
        for (int q = 0; q < KREG; ++q) {
            ulonglong2 av = ub[q];
            u64 wp = dup2(w[q]);
            ffma2(a01, av.x, wp);
            ffma2(a23, av.y, wp);
        }
        if (KSM > 0) {
            const float* wsp = ws + j;
            #pragma unroll 8
            for (int s = 0; s < KSM; ++s) {
                ulonglong2 av = ub[KREG + s];
                u64 wp = dup2(wsp[s * H]);
                ffma2(a01, av.x, wp);
                ffma2(a23, av.y, wp);
            }
        }

        float2 f01 = *(float2*)&a01;
        float2 f23 = *(float2*)&a23;
        float4 hv;
        hv.x = fmaxf(f01.x + bjj, 0.f);
        hv.y = fmaxf(f01.y + bjj, 0.f);
        hv.z = fmaxf(f23.x + bjj, 0.f);
        hv.w = fmaxf(f23.y + bjj, 0.f);
        buf[nb][FIN + j] = hv;
        if (t + 1 < TT) {
            #pragma unroll
            for (int q = 0; q < CNTX; ++q) {
                int i = tid + q * THREADS;
                if (i < BT * FIN)
                    ((float*)buf[nb])[(i % FIN) * 4 + (i / FIN)] = xst[q];
            }
        }
        __stcg(&hout[((b0 + 0) * TT + t) * H + j], hv.x);
        __stcg(&hout[((b0 + 1) * TT + t) * H + j], hv.y);
        __stcg(&hout[((b0 + 2) * TT + t) * H + j], hv.z);
        __stcg(&hout[((b0 + 3) * TT + t) * H + j], hv.w);
        __syncthreads();
        cb = nb;
    }
}

// ============================================================================
// MERGED L3+L4 kernel (NEW): h2 -> h3 -> h4 -> fused dense, all in-CTA.
// 512 threads, BT=4 batch rows. Per step: L3 partials (P3=4 over KV3=384,
// KREG3=56 regs + 40 smem rows), bar, combine3 -> h3 written straight into
// L4's smem act buffer (no DRAM!), bar, L4 partials (P4=8 over KV4=192,
// all 24 weights in regs), bar, combine4 + dense accumulation. 3 barriers
// per step vs 4 split; kills the 128MB h3 round-trip and L4's LDG path.
// ============================================================================
__global__ void __launch_bounds__(512, 1)
rnn_l34(const float* __restrict__ h2,   // [B, T, 256] (layer-2 output)
        const float* __restrict__ Wx3, const float* __restrict__ Wh3,
        const float* __restrict__ b3,
        const float* __restrict__ Wx4, const float* __restrict__ Wh4,
        const float* __restrict__ b4,
        const float* __restrict__ Wd, const float* __restrict__ bd,
        float* __restrict__ out)        // [B]
{
    constexpr int BT = 4;
    constexpr int FIN3 = 256, H3 = 128, KV3 = 384, P3 = 4, KS3 = 96;
    constexpr int KREG3 = 56, KSM3 = KS3 - KREG3;   // 40
    constexpr int H4 = 64, KV4 = 192, P4 = 8, KS4 = 24, KREG4 = 24;
    constexpr int CNTX = (BT * FIN3) / 512;          // 2

    extern __shared__ float ws3[];                   // [P3][KSM3][H3] = 80KB
    __shared__ __align__(16) float4 buf3[2][KV3];    // x: h2 rows 0..255, h: h3 rows 256..383
    __shared__ __align__(16) float4 buf4[KV4];       // x: h3 rows 0..127, h: h4 rows 128..191
    __shared__ float parts3[P3][BT][H3];
    __shared__ float parts4[P4][BT][H4];
    __shared__ float red[512];

    const int tid = threadIdx.x;
    const int b0  = blockIdx.x * BT;
    const int j3  = tid % H3, p3 = tid / H3, k03 = p3 * KS3;
    const int j4  = tid % H4, p4 = tid / H4, k04 = p4 * KS4;

    // L3 weights: 56 in regs, 40 rows in smem
    float w3[KREG3];
    #pragma unroll
    for (int q = 0; q < KREG3; ++q) {
        int v = k03 + q;
        w3[q] = (v < FIN3) ? __ldg(&Wx3[v * H3 + j3]) : __ldg(&Wh3[(v - FIN3) * H3 + j3]);
    }
    for (int idx = tid; idx < P3 * KSM3 * H3; idx += 512) {
        int pp = idx / (KSM3 * H3);
        int rem = idx % (KSM3 * H3);
        int s = rem / H3, jj = rem % H3;
        int v = pp * KS3 + KREG3 + s;
        ws3[idx] = (v < FIN3) ? Wx3[v * H3 + jj] : Wh3[(v - FIN3) * H3 + jj];
    }
    // L4 weights: all 24 in regs
    float w4[KREG4];
    #pragma unroll
    for (int q = 0; q < KREG4; ++q) {
        int v = k04 + q;
        w4[q] = (v < H3) ? __ldg(&Wx4[v * H4 + j4]) : __ldg(&Wh4[(v - H3) * H4 + j4]);
    }
    // zero h3, h4 states
    for (int i = tid; i < H3; i += 512) buf3[0][FIN3 + i] = make_float4(0.f, 0.f, 0.f, 0.f);
    for (int i = tid; i < H4; i += 512) buf4[H3 + i]      = make_float4(0.f, 0.f, 0.f, 0.f);
    // prime h2(t=0)
    #pragma unroll
    for (int q = 0; q < CNTX; ++q) {
        int i = tid + q * 512;
        int r = i / FIN3, k = i % FIN3;
        ((float*)buf3[0])[k * 4 + r] = __ldcg(&h2[((b0 + r) * TT + 0) * FIN3 + k]);
    }
    const float bj3 = b3[j3];
    const float bj4 = (tid < BT * H4) ? b4[tid % H4] : 0.f;

    __syncthreads();

    float dacc = 0.f;
    int cb = 0;

    for (int t = 0; t < TT; ++t) {
        const int nb = cb ^ 1;

        // prefetch h2(t+1)
        float xst[CNTX];
        if (t + 1 < TT) {
            #pragma unroll
            for (int q = 0; q < CNTX; ++q) {
                int i = tid + q * 512;
                xst[q] = __ldcg(&h2[((b0 + i / FIN3) * TT + (t + 1)) * FIN3 + (i % FIN3)]);
            }
        }

        // ---- L3 partials ----
        float a0 = 0.f, a1 = 0.f, a2 = 0.f, a3 = 0.f;
        const float4* ub3 = buf3[cb] + k03;
        #pragma unroll
        for (int q = 0; q < KREG3; ++q) {
            float4 v = ub3[q];
            a0 = fmaf(v.x, w3[q], a0);
            a1 = fmaf(v.y, w3[q], a1);
            a2 = fmaf(v.z, w3[q], a2);
            a3 = fmaf(v.w, w3[q], a3);
        }
        {
            const float* wsp = ws3 + (p3 * KSM3) * H3 + j3;
            #pragma unroll 8
            for (int s = 0; s < KSM3; ++s) {
                float4 v = ub3[KREG3 + s];
                float wv = wsp[s * H3];
                a0 = fmaf(v.x, wv, a0);
                a1 = fmaf(v.y, wv, a1);
                a2 = fmaf(v.z, wv, a2);
                a3 = fmaf(v.w, wv, a3);
            }
        }
        parts3[p3][0][j3] = a0;
        parts3[p3][1][j3] = a1;
        parts3[p3][2][j3] = a2;
        parts3[p3][3][j3] = a3;
        if (t + 1 < TT) {
            #pragma unroll
            for (int q = 0; q < CNTX; ++q) {
                int i = tid + q * 512;
                ((float*)buf3[nb])[(i % FIN3) * 4 + (i / FIN3)] = xst[q];
            }
        }
        __syncthreads();                        // bar1

        // ---- combine3: h3 -> buf3[nb] h-state AND buf4 x (no DRAM) ----
        {
            int r = tid / H3, jj = tid % H3;    // 512 = BT*H3 exactly
            float s = bj3;
            #pragma unroll
            for (int pp = 0; pp < P3; ++pp) s += parts3[pp][r][jj];
            s = fmaxf(s, 0.f);
            ((float*)&buf3[nb][FIN3 + jj])[r] = s;
            ((float*)&buf4[jj])[r] = s;
        }
        __syncthreads();                        // bar2

        // ---- L4 partials ----
        float c0 = 0.f, c1 = 0.f, c2 = 0.f, c3 = 0.f;
        const float4* ub4 = buf4 + k04;
        #pragma unroll
        for (int q = 0; q < KREG4; ++q) {
            float4 v = ub4[q];
            c0 = fmaf(v.x, w4[q], c0);
            c1 = fmaf(v.y, w4[q], c1);
            c2 = fmaf(v.z, w4[q], c2);
            c3 = fmaf(v.w, w4[q], c3);
        }
        parts4[p4][0][j4] = c0;
        parts4[p4][1][j4] = c1;
        parts4[p4][2][j4] = c2;
        parts4[p4][3][j4] = c3;
        __syncthreads();                        // bar3

        // ---- combine4 + fused dense ----
        if (tid < BT * H4) {
            int r = tid / H4, jj = tid % H4;
            float s = bj4;
            #pragma unroll
            for (int pp = 0; pp < P4; ++pp) s += parts4[pp][r][jj];
            s = fmaxf(s, 0.f);
            ((float*)&buf4[H3 + jj])[r] = s;
            dacc = fmaf(s, __ldg(&Wd[t * H4 + jj]), dacc);
        }
        cb = nb;
    }

    red[tid] = dacc;
    __syncthreads();
    if (tid < BT) {
        float s = bd[0];
        #pragma unroll 8
        for (int q = 0; q < H4; ++q) s += red[tid * H4 + q];
        out[b0 + tid] = s;
    }
}

extern "C" void kernel_launch(void* const* d_in, const int* in_sizes, int n_in,
                              void* d_out, int out_size)
{
    (void)in_sizes; (void)n_in; (void)out_size;

    const float* x   = (const float*)d_in[0];
    const float* Wx1 = (const float*)d_in[1];
    const float* Wh1 = (const float*)d_in[2];
    const float* b1  = (const float*)d_in[3];
    const float* Wx2 = (const float*)d_in[4];
    const float* Wh2 = (const float*)d_in[5];
    const float* b2  = (const float*)d_in[6];
    const float* Wx3 = (const float*)d_in[7];
    const float* Wh3 = (const float*)d_in[8];
    const float* b3  = (const float*)d_in[9];
    const float* Wx4 = (const float*)d_in[10];
    const float* Wh4 = (const float*)d_in[11];
    const float* b4  = (const float*)d_in[12];
    const float* Wd  = (const float*)d_in[13];
    const float* bd  = (const float*)d_in[14];
    float* out = (float*)d_out;

    float *bufA = nullptr, *bufB = nullptr;
    cudaGetSymbolAddress((void**)&bufA, g_bufA);
    cudaGetSymbolAddress((void**)&bufB, g_bufB);

    const dim3 grid(BB / 4);   // 128 CTAs

    // Dynamic smem:
    //   L2 (md1):  KSM=192 -> 192*256*4 = 196608 B
    //   L34:       4*40*128*4           = 81920 B
    constexpr int DynL2  = 192 * 256 * 4;
    constexpr int DynL34 = 4 * 40 * 128 * 4;
    cudaFuncSetAttribute(rnn_layer_md1<128, 256, 192, 256>,
                         cudaFuncAttributeMaxDynamicSharedMemorySize, DynL2);
    cudaFuncSetAttribute(rnn_l34,
                         cudaFuncAttributeMaxDynamicSharedMemorySize, DynL34);

    // L1: scalar, 512 thr, P=4, KS=48 all in regs (R8/R10 measured best)
    rnn_layer<64, 128, 4, 48, 512><<<grid, 512, 0>>>(
        x, Wx1, Wh1, b1, bufA);
    // L2: movdup P=1, 256 thr, 192 weight regs + 192 smem rows (R10 best)
    rnn_layer_md1<128, 256, 192, 256><<<grid, 256, DynL2>>>(
        bufA, Wx2, Wh2, b2, bufB);
    // L3+L4 merged (+ fused dense): h2 -> out, h3 never leaves the CTA
    rnn_l34<<<grid, 512, DynL34>>>(
        bufB, Wx3, Wh3, b3, Wx4, Wh4, b4, Wd, bd, out);
}

// round 15
// speedup vs baseline: 1.6053x; 1.6053x over previous
#include <cuda_runtime.h>

#define BB 512
#define TT 256

typedef unsigned long long u64;

// Inter-layer hidden sequences, batch-major [B, T, H]. Max H=256 -> 128 MB each.
__device__ float g_bufA[BB * TT * 256];
__device__ float g_bufB[BB * TT * 256];

__device__ __forceinline__ void ffma2(u64& d, u64 a, u64 b) {
    asm("fma.rn.f32x2 %0, %1, %2, %0;" : "+l"(d) : "l"(a), "l"(b));
}
__device__ __forceinline__ u64 dup2(float w) {
    u64 r;
    unsigned int wu = __float_as_uint(w);
    asm("mov.b64 %0, {%1, %1};" : "=l"(r) : "r"(wu));
    return r;
}

// ============================================================================
// SCALAR kernel (layer 1: R10-exact, 512 thr / P=4, all weights in regs).
// ============================================================================
template<int FIN, int H, int P, int KREG, int THREADS>
__global__ void __launch_bounds__(THREADS, 1)
rnn_layer(const float* __restrict__ x, const float* __restrict__ Wx,
          const float* __restrict__ Wh, const float* __restrict__ bias,
          float* __restrict__ hout)
{
    constexpr int BT  = 4;
    constexpr int KV  = FIN + H;
    constexpr int KS  = KV / P;
    constexpr int KSM = KS - KREG;
    constexpr int CNT  = (BT * H + THREADS - 1) / THREADS;
    constexpr int CNTX = (BT * FIN + THREADS - 1) / THREADS;
    static_assert(H * P == THREADS, "thread count");
    static_assert(KV % P == 0 && KSM >= 0, "k partition");

    extern __shared__ float ws[];                       // [P][KSM][H]
    __shared__ __align__(16) float4 buf[2][KV];
    __shared__ float part[P][BT][H];

    const int tid = threadIdx.x;
    const int j   = tid % H;
    const int p   = tid / H;
    const int b0  = blockIdx.x * BT;
    const int k0  = p * KS;

    float w[KREG > 0 ? KREG : 1];
    #pragma unroll
    for (int q = 0; q < KREG; ++q) {
        int v = k0 + q;
        w[q] = (v < FIN) ? __ldg(&Wx[v * H + j]) : __ldg(&Wh[(v - FIN) * H + j]);
    }
    if (KSM > 0) {
        for (int idx = tid; idx < P * KSM * H; idx += THREADS) {
            int pp = idx / (KSM * H);
            int rem = idx % (KSM * H);
            int s = rem / H, jj = rem % H;
            int v = pp * KS + KREG + s;
            ws[idx] = (v < FIN) ? Wx[v * H + jj] : Wh[(v - FIN) * H + jj];
        }
    }
    for (int i = tid; i < H; i += THREADS) buf[0][FIN + i] = make_float4(0.f, 0.f, 0.f, 0.f);
    #pragma unroll
    for (int q = 0; q < CNTX; ++q) {
        int i = tid + q * THREADS;
        if (i < BT * FIN) {
            int r = i / FIN, k = i % FIN;
            ((float*)buf[0])[k * 4 + r] = __ldcg(&x[((b0 + r) * TT + 0) * FIN + k]);
        }
    }
    float bj[CNT];
    #pragma unroll
    for (int q = 0; q < CNT; ++q) {
        int e = tid + q * THREADS;
        bj[q] = (e < BT * H) ? bias[e % H] : 0.f;
    }

    __syncthreads();

    int cb = 0;

    for (int t = 0; t < TT; ++t) {
        const int nb = cb ^ 1;

        float xst[CNTX];
        if (t + 1 < TT) {
            #pragma unroll
            for (int q = 0; q < CNTX; ++q) {
                int i = tid + q * THREADS;
                if (i < BT * FIN)
                    xst[q] = __ldcg(&x[((b0 + i / FIN) * TT + (t + 1)) * FIN + (i % FIN)]);
            }
        }

        float a0 = 0.f, a1 = 0.f, a2 = 0.f, a3 = 0.f;
        const float4* ub = buf[cb] + k0;

        #pragma unroll
        for (int q = 0; q < KREG; ++q) {
            float4 v = ub[q];
            a0 = fmaf(v.x, w[q], a0);
            a1 = fmaf(v.y, w[q], a1);
            a2 = fmaf(v.z, w[q], a2);
            a3 = fmaf(v.w, w[q], a3);
        }
        if (KSM > 0) {
            const float* wsp = ws + (p * KSM) * H + j;
            #pragma unroll 8
            for (int s = 0; s < KSM; ++s) {
                float4 v = ub[KREG + s];
                float wv = wsp[s * H];
                a0 = fmaf(v.x, wv, a0);
                a1 = fmaf(v.y, wv, a1);
                a2 = fmaf(v.z, wv, a2);
                a3 = fmaf(v.w, wv, a3);
            }
        }

        part[p][0][j] = a0;
        part[p][1][j] = a1;
        part[p][2][j] = a2;
        part[p][3][j] = a3;
        if (t + 1 < TT) {
            #pragma unroll
            for (int q = 0; q < CNTX; ++q) {
                int i = tid + q * THREADS;
                if (i < BT * FIN)
                    ((float*)buf[nb])[(i % FIN) * 4 + (i / FIN)] = xst[q];
            }
        }
        __syncthreads();

        #pragma unroll
        for (int q = 0; q < CNT; ++q) {
            int e = tid + q * THREADS;
            if (e < BT * H) {
                int r = e / H, jj = e % H;
                float s = bj[q];
                #pragma unroll
                for (int pp = 0; pp < P; ++pp) s += part[pp][r][jj];
                s = fmaxf(s, 0.f);
                ((float*)buf[nb])[(FIN + jj) * 4 + r] = s;
                __stcg(&hout[((b0 + r) * TT + t) * H + jj], s);
            }
        }
        __syncthreads();
        cb = nb;
    }
}

// ============================================================================
// MOVDUP-FFMA2, P==1 (layer 2: R10-exact, measured ~820us). One barrier/step.
// ============================================================================
template<int FIN, int H, int KREG, int THREADS>
__global__ void __launch_bounds__(THREADS, 1)
rnn_layer_md1(const float* __restrict__ x, const float* __restrict__ Wx,
              const float* __restrict__ Wh, const float* __restrict__ bias,
              float* __restrict__ hout)
{
    constexpr int BT  = 4;
    constexpr int KV  = FIN + H;
    constexpr int KSM = KV - KREG;
    constexpr int CNTX = (BT * FIN + THREADS - 1) / THREADS;
    static_assert(H == THREADS, "P==1: one thread per column");
    static_assert(KSM >= 0, "k partition");

    extern __shared__ float ws[];                       // [KSM][H]
    __shared__ __align__(16) float4 buf[2][KV];

    const int tid = threadIdx.x;
    const int j   = tid;
    const int b0  = blockIdx.x * BT;

    float w[KREG];
    #pragma unroll
    for (int q = 0; q < KREG; ++q) {
        int v = q;
        w[q] = (v < FIN) ? __ldg(&Wx[v * H + j]) : __ldg(&Wh[(v - FIN) * H + j]);
    }
    if (KSM > 0) {
        for (int idx = tid; idx < KSM * H; idx += THREADS) {
            int s = idx / H, jj = idx % H;
            int v = KREG + s;
            ws[idx] = (v < FIN) ? Wx[v * H + jj] : Wh[(v - FIN) * H + jj];
        }
    }
    for (int i = tid; i < H; i += THREADS) buf[0][FIN + i] = make_float4(0.f, 0.f, 0.f, 0.f);
    #pragma unroll
    for (int q = 0; q < CNTX; ++q) {
        int i = tid + q * THREADS;
        if (i < BT * FIN) {
            int r = i / FIN, k = i % FIN;
            ((float*)buf[0])[k * 4 + r] = __ldcg(&x[((b0 + r) * TT + 0) * FIN + k]);
        }
    }
    const float bjj = bias[j];

    __syncthreads();

    int cb = 0;

    for (int t = 0; t < TT; ++t) {
        const int nb = cb ^ 1;

        float xst[CNTX];
        if (t + 1 < TT) {
            #pragma unroll
            for (int q = 0; q < CNTX; ++q) {
                int i = tid + q * THREADS;
                if (i < BT * FIN)
                    xst[q] = __ldcg(&x[((b0 + i / FIN) * TT + (t + 1)) * FIN + (i % FIN)]);
            }
        }

        u64 a01 = 0, a23 = 0;
        const ulonglong2* ub = (const ulonglong2*)buf[cb];

        #pragma unroll
        for (int q = 0; q < KREG; ++q) {
            ulonglong2 av = ub[q];
            u64 wp = dup2(w[q]);
            ffma2(a01, av.x, wp);
            ffma2(a23, av.y, wp);
        }
        if (KSM > 0) {
            const float* wsp = ws + j;
            #pragma unroll 8
            for (int s = 0; s < KSM; ++s) {
                ulonglong2 av = ub[KREG + s];
                u64 wp = dup2(wsp[s * H]);
                ffma2(a01, av.x, wp);
                ffma2(a23, av.y, wp);
            }
        }

        float2 f01 = *(float2*)&a01;
        float2 f23 = *(float2*)&a23;
        float4 hv;
        hv.x = fmaxf(f01.x + bjj, 0.f);
        hv.y = fmaxf(f01.y + bjj, 0.f);
        hv.z = fmaxf(f23.x + bjj, 0.f);
        hv.w = fmaxf(f23.y + bjj, 0.f);
        buf[nb][FIN + j] = hv;
        if (t + 1 < TT) {
            #pragma unroll
            for (int q = 0; q < CNTX; ++q) {
                int i = tid + q * THREADS;
                if (i < BT * FIN)
                    ((float*)buf[nb])[(i % FIN) * 4 + (i / FIN)] = xst[q];
            }
        }
        __stcg(&hout[((b0 + 0) * TT + t) * H + j], hv.x);
        __stcg(&hout[((b0 + 1) * TT + t) * H + j], hv.y);
        __stcg(&hout[((b0 + 2) * TT + t) * H + j], hv.z);
        __stcg(&hout[((b0 + 3) * TT + t) * H + j], hv.w);
        __syncthreads();
        cb = nb;
    }
}

// ============================================================================
// MERGED L3+L4 kernel, SPILL-FIXED: KREG3 56->32 (w3[32]+w4[24]=56 weight
// regs, ~100 total, under the 128/thread cap at 512 threads; the R13 version
// at 80 weight regs spilled and reloaded from local in the unrolled hot loop).
// Dataflow unchanged from R13 (verified correct): per step L3 partials, bar,
// combine3 -> h3 straight into L4's smem buffer (no DRAM), bar, L4 partials,
// bar, combine4 + fused dense.
// ============================================================================
__global__ void __launch_bounds__(512, 1)
rnn_l34(const float* __restrict__ h2,   // [B, T, 256]
        const float* __restrict__ Wx3, const float* __restrict__ Wh3,
        const float* __restrict__ b3,
        const float* __restrict__ Wx4, const float* __restrict__ Wh4,
        const float* __restrict__ b4,
        const float* __restrict__ Wd, const float* __restrict__ bd,
        float* __restrict__ out)        // [B]
{
    constexpr int BT = 4;
    constexpr int FIN3 = 256, H3 = 128, P3 = 4, KS3 = 96;
    constexpr int KREG3 = 32, KSM3 = KS3 - KREG3;   // 64
    constexpr int H4 = 64, P4 = 8, KREG4 = 24;      // KV4=192, KS4=24 all-reg
    constexpr int CNTX = (BT * FIN3) / 512;          // 2

    extern __shared__ float ws3[];                   // [P3][KSM3][H3] = 128KB
    __shared__ __align__(16) float4 buf3[2][FIN3 + H3];
    __shared__ __align__(16) float4 buf4[H3 + H4];
    __shared__ float parts3[P3][BT][H3];
    __shared__ float parts4[P4][BT][H4];
    __shared__ float red[512];

    const int tid = threadIdx.x;
    const int b0  = blockIdx.x * BT;
    const int j3  = tid % H3, p3 = tid / H3, k03 = p3 * KS3;
    const int j4  = tid % H4, p4 = tid / H4, k04 = p4 * 24;

    float w3[KREG3];
    #pragma unroll
    for (int q = 0; q < KREG3; ++q) {
        int v = k03 + q;
        w3[q] = (v < FIN3) ? __ldg(&Wx3[v * H3 + j3]) : __ldg(&Wh3[(v - FIN3) * H3 + j3]);
    }
    for (int idx = tid; idx < P3 * KSM3 * H3; idx += 512) {
        int pp = idx / (KSM3 * H3);
        int rem = idx % (KSM3 * H3);
        int s = rem / H3, jj = rem % H3;
        int v = pp * KS3 + KREG3 + s;
        ws3[idx] = (v < FIN3) ? Wx3[v * H3 + jj] : Wh3[(v - FIN3) * H3 + jj];
    }
    float w4[KREG4];
    #pragma unroll
    for (int q = 0; q < KREG4; ++q) {
        int v = k04 + q;
        w4[q] = (v < H3) ? __ldg(&Wx4[v * H4 + j4]) : __ldg(&Wh4[(v - H3) * H4 + j4]);
    }
    for (int i = tid; i < H3; i += 512) buf3[0][FIN3 + i] = make_float4(0.f, 0.f, 0.f, 0.f);
    for (int i = tid; i < H4; i += 512) buf4[H3 + i]      = make_float4(0.f, 0.f, 0.f, 0.f);
    #pragma unroll
    for (int q = 0; q < CNTX; ++q) {
        int i = tid + q * 512;
        int r = i / FIN3, k = i % FIN3;
        ((float*)buf3[0])[k * 4 + r] = __ldcg(&h2[((b0 + r) * TT + 0) * FIN3 + k]);
    }
    const float bj3 = b3[j3];
    const float bj4 = (tid < BT * H4) ? b4[tid % H4] : 0.f;

    __syncthreads();

    float dacc = 0.f;
    int cb = 0;

    for (int t = 0; t < TT; ++t) {
        const int nb = cb ^ 1;

        float xst[CNTX];
        if (t + 1 < TT) {
            #pragma unroll
            for (int q = 0; q < CNTX; ++q) {
                int i = tid + q * 512;
                xst[q] = __ldcg(&h2[((b0 + i / FIN3) * TT + (t + 1)) * FIN3 + (i % FIN3)]);
            }
        }

        // ---- L3 partials ----
        float a0 = 0.f, a1 = 0.f, a2 = 0.f, a3 = 0.f;
        const float4* ub3 = buf3[cb] + k03;
        #pragma unroll
        for (int q = 0; q < KREG3; ++q) {
            float4 v = ub3[q];
            a0 = fmaf(v.x, w3[q], a0);
            a1 = fmaf(v.y, w3[q], a1);
            a2 = fmaf(v.z, w3[q], a2);
            a3 = fmaf(v.w, w3[q], a3);
        }
        {
            const float* wsp = ws3 + (p3 * KSM3) * H3 + j3;
            #pragma unroll 8
            for (int s = 0; s < KSM3; ++s) {
                float4 v = ub3[KREG3 + s];
                float wv = wsp[s * H3];
                a0 = fmaf(v.x, wv, a0);
                a1 = fmaf(v.y, wv, a1);
                a2 = fmaf(v.z, wv, a2);
                a3 = fmaf(v.w, wv, a3);
            }
        }
        parts3[p3][0][j3] = a0;
        parts3[p3][1][j3] = a1;
        parts3[p3][2][j3] = a2;
        parts3[p3][3][j3] = a3;
        if (t + 1 < TT) {
            #pragma unroll
            for (int q = 0; q < CNTX; ++q) {
                int i = tid + q * 512;
                ((float*)buf3[nb])[(i % FIN3) * 4 + (i / FIN3)] = xst[q];
            }
        }
        __syncthreads();                        // bar1

        // ---- combine3: h3 -> buf3[nb] h-state AND buf4 x (no DRAM) ----
        {
            int r = tid / H3, jj = tid % H3;    // 512 = BT*H3 exactly
            float s = bj3;
            #pragma unroll
            for (int pp = 0; pp < P3; ++pp) s += parts3[pp][r][jj];
            s = fmaxf(s, 0.f);
            ((float*)&buf3[nb][FIN3 + jj])[r] = s;
            ((float*)&buf4[jj])[r] = s;
        }
        __syncthreads();                        // bar2

        // ---- L4 partials ----
        float c0 = 0.f, c1 = 0.f, c2 = 0.f, c3 = 0.f;
        const float4* ub4 = buf4 + k04;
        #pragma unroll
        for (int q = 0; q < KREG4; ++q) {
            float4 v = ub4[q];
            c0 = fmaf(v.x, w4[q], c0);
            c1 = fmaf(v.y, w4[q], c1);
            c2 = fmaf(v.z, w4[q], c2);
            c3 = fmaf(v.w, w4[q], c3);
        }
        parts4[p4][0][j4] = c0;
        parts4[p4][1][j4] = c1;
        parts4[p4][2][j4] = c2;
        parts4[p4][3][j4] = c3;
        __syncthreads();                        // bar3

        // ---- combine4 + fused dense ----
        if (tid < BT * H4) {
            int r = tid / H4, jj = tid % H4;
            float s = bj4;
            #pragma unroll
            for (int pp = 0; pp < P4; ++pp) s += parts4[pp][r][jj];
            s = fmaxf(s, 0.f);
            ((float*)&buf4[H3 + jj])[r] = s;
            dacc = fmaf(s, __ldg(&Wd[t * H4 + jj]), dacc);
        }
        cb = nb;
    }

    red[tid] = dacc;
    __syncthreads();
    if (tid < BT) {
        float s = bd[0];
        #pragma unroll 8
        for (int q = 0; q < H4; ++q) s += red[tid * H4 + q];
        out[b0 + tid] = s;
    }
}

extern "C" void kernel_launch(void* const* d_in, const int* in_sizes, int n_in,
                              void* d_out, int out_size)
{
    (void)in_sizes; (void)n_in; (void)out_size;

    const float* x   = (const float*)d_in[0];
    const float* Wx1 = (const float*)d_in[1];
    const float* Wh1 = (const float*)d_in[2];
    const float* b1  = (const float*)d_in[3];
    const float* Wx2 = (const float*)d_in[4];
    const float* Wh2 = (const float*)d_in[5];
    const float* b2  = (const float*)d_in[6];
    const float* Wx3 = (const float*)d_in[7];
    const float* Wh3 = (const float*)d_in[8];
    const float* b3  = (const float*)d_in[9];
    const float* Wx4 = (const float*)d_in[10];
    const float* Wh4 = (const float*)d_in[11];
    const float* b4  = (const float*)d_in[12];
    const float* Wd  = (const float*)d_in[13];
    const float* bd  = (const float*)d_in[14];
    float* out = (float*)d_out;

    float *bufA = nullptr, *bufB = nullptr;
    cudaGetSymbolAddress((void**)&bufA, g_bufA);
    cudaGetSymbolAddress((void**)&bufB, g_bufB);

    const dim3 grid(BB / 4);   // 128 CTAs

    // Dynamic smem:
    //   L2 (md1): KSM=192 -> 192*256*4 = 196608 B
    //   L34:      4*64*128*4           = 131072 B
    constexpr int DynL2  = 192 * 256 * 4;
    constexpr int DynL34 = 4 * 64 * 128 * 4;
    cudaFuncSetAttribute(rnn_layer_md1<128, 256, 192, 256>,
                         cudaFuncAttributeMaxDynamicSharedMemorySize, DynL2);
    cudaFuncSetAttribute(rnn_l34,
                         cudaFuncAttributeMaxDynamicSharedMemorySize, DynL34);

    // L1: scalar, 512 thr, P=4, KS=48 all in regs (R10-exact)
    rnn_layer<64, 128, 4, 48, 512><<<grid, 512, 0>>>(
        x, Wx1, Wh1, b1, bufA);
    // L2: movdup P=1, 256 thr, 192 weight regs + 192 smem rows (R10-exact)
    rnn_layer_md1<128, 256, 192, 256><<<grid, 256, DynL2>>>(
        bufA, Wx2, Wh2, b2, bufB);
    // L3+L4 merged (+ fused dense), spill-fixed: KREG3=32
    rnn_l34<<<grid, 512, DynL34>>>(
        bufB, Wx3, Wh3, b3, Wx4, Wh4, b4, Wd, bd, out);
}

// round 16
// speedup vs baseline: 1.6695x; 1.0400x over previous
#include <cuda_runtime.h>

#define BB 512
#define TT 256

typedef unsigned long long u64;

// Inter-layer hidden sequences, batch-major [B, T, H]. Max H=256 -> 128 MB each.
__device__ float g_bufA[BB * TT * 256];
__device__ float g_bufB[BB * TT * 256];

__device__ __forceinline__ void ffma2(u64& d, u64 a, u64 b) {
    // packed fp32x2 fma: d.lo += a.lo*b.lo ; d.hi += a.hi*b.hi
    asm("fma.rn.f32x2 %0, %1, %2, %0;" : "+l"(d) : "l"(a), "l"(b));
}

// ============================================================================
// SCALAR kernel (R10-exact; measured best for L1/L3/L4).
// ============================================================================
template<int FIN, int H, int P, int KREG, int THREADS, bool FUSE_DENSE>
__global__ void __launch_bounds__(THREADS, 1)
rnn_layer(const float* __restrict__ x, const float* __restrict__ Wx,
          const float* __restrict__ Wh, const float* __restrict__ bias,
          float* __restrict__ hout, const float* __restrict__ Wd,
          const float* __restrict__ bd, float* __restrict__ out)
{
    constexpr int BT  = 4;
    constexpr int KV  = FIN + H;
    constexpr int KS  = KV / P;
    constexpr int KSM = KS - KREG;
    constexpr int CNT  = (BT * H + THREADS - 1) / THREADS;
    constexpr int CNTX = (BT * FIN + THREADS - 1) / THREADS;
    constexpr int REDN = FUSE_DENSE ? THREADS : 1;
    static_assert(H * P == THREADS, "thread count");
    static_assert(KV % P == 0 && KSM >= 0, "k partition");
    static_assert(!FUSE_DENSE || CNT == 1, "dense fusion assumes CNT==1");

    extern __shared__ float ws[];                       // [P][KSM][H]
    __shared__ __align__(16) float4 buf[2][KV];
    __shared__ float part[(P > 1 ? P : 1)][BT][(P > 1 ? H : 1)];
    __shared__ float red[REDN];

    const int tid = threadIdx.x;
    const int j   = tid % H;
    const int p   = tid / H;
    const int b0  = blockIdx.x * BT;
    const int k0  = p * KS;

    float w[KREG > 0 ? KREG : 1];
    #pragma unroll
    for (int q = 0; q < KREG; ++q) {
        int v = k0 + q;
        w[q] = (v < FIN) ? __ldg(&Wx[v * H + j]) : __ldg(&Wh[(v - FIN) * H + j]);
    }
    if (KSM > 0) {
        for (int idx = tid; idx < P * KSM * H; idx += THREADS) {
            int pp = idx / (KSM * H);
            int rem = idx % (KSM * H);
            int s = rem / H, jj = rem % H;
            int v = pp * KS + KREG + s;
            ws[idx] = (v < FIN) ? Wx[v * H + jj] : Wh[(v - FIN) * H + jj];
        }
    }
    for (int i = tid; i < H; i += THREADS) buf[0][FIN + i] = make_float4(0.f, 0.f, 0.f, 0.f);
    #pragma unroll
    for (int q = 0; q < CNTX; ++q) {
        int i = tid + q * THREADS;
        if (i < BT * FIN) {
            int r = i / FIN, k = i % FIN;
            ((float*)buf[0])[k * 4 + r] = __ldcg(&x[((b0 + r) * TT + 0) * FIN + k]);
        }
    }

    const float bjj = bias[j];
    float bj[CNT];
    #pragma unroll
    for (int q = 0; q < CNT; ++q) {
        int e = tid + q * THREADS;
        bj[q] = (e < BT * H) ? bias[e % H] : 0.f;
    }

    __syncthreads();

    float dacc = 0.f;
    int cb = 0;

    for (int t = 0; t < TT; ++t) {
        const int nb = cb ^ 1;

        float xst[CNTX];
        if (t + 1 < TT) {
            #pragma unroll
            for (int q = 0; q < CNTX; ++q) {
                int i = tid + q * THREADS;
                if (i < BT * FIN)
                    xst[q] = __ldcg(&x[((b0 + i / FIN) * TT + (t + 1)) * FIN + (i % FIN)]);
            }
        }

        float a0 = 0.f, a1 = 0.f, a2 = 0.f, a3 = 0.f;
        const float4* ub = buf[cb] + k0;

        #pragma unroll
        for (int q = 0; q < KREG; ++q) {
            float4 v = ub[q];
            a0 = fmaf(v.x, w[q], a0);
            a1 = fmaf(v.y, w[q], a1);
            a2 = fmaf(v.z, w[q], a2);
            a3 = fmaf(v.w, w[q], a3);
        }
        if (KSM > 0) {
            const float* wsp = ws + (p * KSM) * H + j;
            #pragma unroll 8
            for (int s = 0; s < KSM; ++s) {
                float4 v = ub[KREG + s];
                float wv = wsp[s * H];
                a0 = fmaf(v.x, wv, a0);
                a1 = fmaf(v.y, wv, a1);
                a2 = fmaf(v.z, wv, a2);
                a3 = fmaf(v.w, wv, a3);
            }
        }

        if (P == 1) {
            float4 hv;
            hv.x = fmaxf(a0 + bjj, 0.f);
            hv.y = fmaxf(a1 + bjj, 0.f);
            hv.z = fmaxf(a2 + bjj, 0.f);
            hv.w = fmaxf(a3 + bjj, 0.f);
            buf[nb][FIN + j] = hv;
            if (t + 1 < TT) {
                #pragma unroll
                for (int q = 0; q < CNTX; ++q) {
                    int i = tid + q * THREADS;
                    if (i < BT * FIN)
                        ((float*)buf[nb])[(i % FIN) * 4 + (i / FIN)] = xst[q];
                }
            }
            __stcg(&hout[((b0 + 0) * TT + t) * H + j], hv.x);
            __stcg(&hout[((b0 + 1) * TT + t) * H + j], hv.y);
            __stcg(&hout[((b0 + 2) * TT + t) * H + j], hv.z);
            __stcg(&hout[((b0 + 3) * TT + t) * H + j], hv.w);
            __syncthreads();
        } else {
            part[p][0][j] = a0;
            part[p][1][j] = a1;
            part[p][2][j] = a2;
            part[p][3][j] = a3;
            if (t + 1 < TT) {
                #pragma unroll
                for (int q = 0; q < CNTX; ++q) {
                    int i = tid + q * THREADS;
                    if (i < BT * FIN)
                        ((float*)buf[nb])[(i % FIN) * 4 + (i / FIN)] = xst[q];
                }
            }
            __syncthreads();
            #pragma unroll
            for (int q = 0; q < CNT; ++q) {
                int e = tid + q * THREADS;
                if (e < BT * H) {
                    int r = e / H, jj = e % H;
                    float s = bj[q];
                    #pragma unroll
                    for (int pp = 0; pp < P; ++pp) s += part[pp][r][jj];
                    s = fmaxf(s, 0.f);
                    ((float*)buf[nb])[(FIN + jj) * 4 + r] = s;
                    if (FUSE_DENSE) {
                        dacc = fmaf(s, __ldg(&Wd[t * H + jj]), dacc);
                    } else {
                        __stcg(&hout[((b0 + r) * TT + t) * H + jj], s);
                    }
                }
            }
            __syncthreads();
        }
        cb = nb;
    }

    if (FUSE_DENSE) {
        red[tid] = dacc;
        __syncthreads();
        if (tid < BT) {
            float s = bd[0];
            #pragma unroll 8
            for (int q = 0; q < H; ++q) s += red[tid * H + q];
            out[b0 + tid] = s;
        }
    }
}

// ============================================================================
// K-PAIR FFMA2 kernel for layer 2 (P==1, 256 thr). NO dup movs:
//   - weight u64 regs hold (W_k, W_{k+1}) for ADJACENT k rows (each weight
//     stored once; 96 u64 = 192 regs = same footprint as scalar md1)
//   - acts stored row-major as (a_k, a_{k+1}) float2 pairs per batch row;
//     one broadcast LDS.128 per (row, 4k-block) feeds 2 FFMA2 directly
//   - smem weights pre-packed as float4 quads (W_4s..W_4s+3) per column,
//     coalesced LDS.128
// Per 4k-block (16 MACs): 4 LDS.128 + 8 FFMA2 = 12 instr (reg) / 13 (smem).
// fma-pipe floor 3072 cyc/step becomes the binding term.
// ============================================================================
template<int FIN, int H, int KREGROWS, int THREADS>
__global__ void __launch_bounds__(THREADS, 1)
rnn_layer_kp(const float* __restrict__ x, const float* __restrict__ Wx,
             const float* __restrict__ Wh, const float* __restrict__ bias,
             float* __restrict__ hout)
{
    constexpr int BT   = 4;
    constexpr int KV   = FIN + H;          // 384
    constexpr int KSMR = KV - KREGROWS;    // smem rows (192)
    constexpr int NRQ  = KREGROWS / 4;     // reg quad-blocks (48)
    constexpr int NSQ  = KSMR / 4;         // smem quad-blocks (48)
    constexpr int NWP  = KREGROWS / 2;     // reg u64 weight pairs (96)
    constexpr int CNTX = (BT * FIN + THREADS - 1) / THREADS;
    static_assert(H == THREADS, "P==1: one thread per column");
    static_assert(KREGROWS % 4 == 0 && KSMR % 4 == 0 && FIN % 4 == 0, "quads");

    extern __shared__ float4 wq[];                 // [NSQ][H]: (W4s..W4s+3) per col
    __shared__ __align__(16) float2 abuf[2][BT][KV / 2];   // (a_2q, a_2q+1) pairs

    const int tid = threadIdx.x;
    const int j   = tid;
    const int b0  = blockIdx.x * BT;

    // ---- one-time: reg weight pairs (rows 0..KREGROWS) ----
    u64 w[NWP];
    #pragma unroll
    for (int q = 0; q < NWP; ++q) {
        int k = 2 * q;
        float lo = (k     < FIN) ? __ldg(&Wx[k * H + j])       : __ldg(&Wh[(k - FIN) * H + j]);
        float hi = (k + 1 < FIN) ? __ldg(&Wx[(k + 1) * H + j]) : __ldg(&Wh[(k + 1 - FIN) * H + j]);
        float2 tpack = make_float2(lo, hi);
        w[q] = *(const u64*)&tpack;
    }
    // ---- one-time: smem weight quads (rows KREGROWS..KV) ----
    for (int idx = tid; idx < NSQ * H; idx += THREADS) {
        int s = idx / H, jj = idx % H;
        int v = KREGROWS + 4 * s;
        float w0 = (v     < FIN) ? Wx[v * H + jj]       : Wh[(v - FIN) * H + jj];
        float w1 = (v + 1 < FIN) ? Wx[(v + 1) * H + jj] : Wh[(v + 1 - FIN) * H + jj];
        float w2 = (v + 2 < FIN) ? Wx[(v + 2) * H + jj] : Wh[(v + 2 - FIN) * H + jj];
        float w3 = (v + 3 < FIN) ? Wx[(v + 3) * H + jj] : Wh[(v + 3 - FIN) * H + jj];
        wq[idx] = make_float4(w0, w1, w2, w3);
    }
    // h_0 = 0
    for (int i = tid; i < BT * H; i += THREADS) {
        int r = i / H, k = i % H;
        ((float*)abuf[0][r])[FIN + k] = 0.f;
    }
    // prime x(t=0)
    #pragma unroll
    for (int q = 0; q < CNTX; ++q) {
        int i = tid + q * THREADS;
        if (i < BT * FIN) {
            int r = i / FIN, k = i % FIN;
            ((float*)abuf[0][r])[k] = __ldcg(&x[((b0 + r) * TT + 0) * FIN + k]);
        }
    }
    const float bjj = bias[j];

    __syncthreads();

    int cb = 0;

    for (int t = 0; t < TT; ++t) {
        const int nb = cb ^ 1;

        // prefetch x(t+1)
        float xst[CNTX];
        if (t + 1 < TT) {
            #pragma unroll
            for (int q = 0; q < CNTX; ++q) {
                int i = tid + q * THREADS;
                if (i < BT * FIN)
                    xst[q] = __ldcg(&x[((b0 + i / FIN) * TT + (t + 1)) * FIN + (i % FIN)]);
            }
        }

        u64 acc0 = 0, acc1 = 0, acc2 = 0, acc3 = 0;   // (even-k, odd-k) per row
        const ulonglong2* a0p = (const ulonglong2*)abuf[cb][0];
        const ulonglong2* a1p = (const ulonglong2*)abuf[cb][1];
        const ulonglong2* a2p = (const ulonglong2*)abuf[cb][2];
        const ulonglong2* a3p = (const ulonglong2*)abuf[cb][3];

        // reg-weight quad blocks (rows 0..KREGROWS): 4 LDS.128 + 8 FFMA2 each
        #pragma unroll
        for (int s = 0; s < NRQ; ++s) {
            ulonglong2 v0 = a0p[s];
            ulonglong2 v1 = a1p[s];
            ulonglong2 v2 = a2p[s];
            ulonglong2 v3 = a3p[s];
            ffma2(acc0, v0.x, w[2 * s]);
            ffma2(acc1, v1.x, w[2 * s]);
            ffma2(acc2, v2.x, w[2 * s]);
            ffma2(acc3, v3.x, w[2 * s]);
            ffma2(acc0, v0.y, w[2 * s + 1]);
            ffma2(acc1, v1.y, w[2 * s + 1]);
            ffma2(acc2, v2.y, w[2 * s + 1]);
            ffma2(acc3, v3.y, w[2 * s + 1]);
        }
        // smem-weight quad blocks: + 1 coalesced LDS.128 for the weight quad
        {
            const float4* wqp = wq + j;
            #pragma unroll 8
            for (int s = 0; s < NSQ; ++s) {
                float4 wv = wqp[s * H];
                u64 wlo = *(const u64*)&wv.x;
                u64 whi = *(const u64*)&wv.z;
                ulonglong2 v0 = a0p[NRQ + s];
                ulonglong2 v1 = a1p[NRQ + s];
                ulonglong2 v2 = a2p[NRQ + s];
                ulonglong2 v3 = a3p[NRQ + s];
                ffma2(acc0, v0.x, wlo);
                ffma2(acc1, v1.x, wlo);
                ffma2(acc2, v2.x, wlo);
                ffma2(acc3, v3.x, wlo);
                ffma2(acc0, v0.y, whi);
                ffma2(acc1, v1.y, whi);
                ffma2(acc2, v2.y, whi);
                ffma2(acc3, v3.y, whi);
            }
        }

        // epilogue: fold (even,odd) lanes, bias, relu, state + output
        float2 f0 = *(float2*)&acc0;
        float2 f1 = *(float2*)&acc1;
        float2 f2 = *(float2*)&acc2;
        float2 f3 = *(float2*)&acc3;
        float h0 = fmaxf(f0.x + f0.y + bjj, 0.f);
        float h1 = fmaxf(f1.x + f1.y + bjj, 0.f);
        float h2v = fmaxf(f2.x + f2.y + bjj, 0.f);
        float h3v = fmaxf(f3.x + f3.y + bjj, 0.f);
        ((float*)abuf[nb][0])[FIN + j] = h0;
        ((float*)abuf[nb][1])[FIN + j] = h1;
        ((float*)abuf[nb][2])[FIN + j] = h2v;
        ((float*)abuf[nb][3])[FIN + j] = h3v;
        if (t + 1 < TT) {
            #pragma unroll
            for (int q = 0; q < CNTX; ++q) {
                int i = tid + q * THREADS;
                if (i < BT * FIN)
                    ((float*)abuf[nb][i / FIN])[i % FIN] = xst[q];
            }
        }
        __stcg(&hout[((b0 + 0) * TT + t) * H + j], h0);
        __stcg(&hout[((b0 + 1) * TT + t) * H + j], h1);
        __stcg(&hout[((b0 + 2) * TT + t) * H + j], h2v);
        __stcg(&hout[((b0 + 3) * TT + t) * H + j], h3v);
        __syncthreads();                  // ONE barrier per step
        cb = nb;
    }
}

extern "C" void kernel_launch(void* const* d_in, const int* in_sizes, int n_in,
                              void* d_out, int out_size)
{
    (void)in_sizes; (void)n_in; (void)out_size;

    const float* x   = (const float*)d_in[0];
    const float* Wx1 = (const float*)d_in[1];
    const float* Wh1 = (const float*)d_in[2];
    const float* b1  = (const float*)d_in[3];
    const float* Wx2 = (const float*)d_in[4];
    const float* Wh2 = (const float*)d_in[5];
    const float* b2  = (const float*)d_in[6];
    const float* Wx3 = (const float*)d_in[7];
    const float* Wh3 = (const float*)d_in[8];
    const float* b3  = (const float*)d_in[9];
    const float* Wx4 = (const float*)d_in[10];
    const float* Wh4 = (const float*)d_in[11];
    const float* b4  = (const float*)d_in[12];
    const float* Wd  = (const float*)d_in[13];
    const float* bd  = (const float*)d_in[14];
    float* out = (float*)d_out;

    float *bufA = nullptr, *bufB = nullptr;
    cudaGetSymbolAddress((void**)&bufA, g_bufA);
    cudaGetSymbolAddress((void**)&bufB, g_bufB);

    const dim3 grid(BB / 4);   // 128 CTAs

    // Dynamic smem:
    //   L2 (kp): 48 quads * 256 cols * 16B = 196608 B
    //   L3:      4*16*128*4                = 32768 B
    constexpr int DynL2 = 48 * 256 * 16;
    constexpr int DynL3 = 4 * 16 * 128 * 4;
    cudaFuncSetAttribute(rnn_layer_kp<128, 256, 192, 256>,
                         cudaFuncAttributeMaxDynamicSharedMemorySize, DynL2);
    cudaFuncSetAttribute(rnn_layer<256, 128, 4, 80, 512, false>,
                         cudaFuncAttributeMaxDynamicSharedMemorySize, DynL3);

    // L1: scalar, 512 thr, P=4, KS=48 all in regs (R10-exact)
    rnn_layer<64, 128, 4, 48, 512, false><<<grid, 512, 0>>>(
        x, Wx1, Wh1, b1, bufA, nullptr, nullptr, nullptr);
    // L2: k-pair FFMA2, 256 thr, P=1, 96 u64 reg pairs + 48 smem quads
    rnn_layer_kp<128, 256, 192, 256><<<grid, 256, DynL2>>>(
        bufA, Wx2, Wh2, b2, bufB);
    // L3: scalar, 512 thr, P=4, 80 regs + 16 smem rows (R10-exact)
    rnn_layer<256, 128, 4, 80, 512, false><<<grid, 512, DynL3>>>(
        bufB, Wx3, Wh3, b3, bufA, nullptr, nullptr, nullptr);
    // L4: scalar, 256 thr, P=4, KS=48 all in regs, fused dense (R10-exact)
    rnn_layer<128, 64, 4, 48, 256, true><<<grid, 256, 0>>>(
        bufA, Wx4, Wh4, b4, nullptr, Wd, bd, out);
}